// round 1
// baseline (speedup 1.0000x reference)
#include <cuda_runtime.h>
#include <math.h>

#define Bn   8
#define Sn   1024
#define Dm   128
#define Hn   8
#define HD   16
#define FFn  256
#define Lnum 4
#define LWn  128
#define EPSf 1e-5f
#define ROWS (Bn * Sn)   // 8192

// ---------------- scratch (static device memory; no runtime allocs) ----------------
__device__ float g_x[ROWS * Dm];
__device__ float g_y[ROWS * Dm];
__device__ float g_qkv[ROWS * 3 * Dm];
__device__ float g_ctx[ROWS * Dm];
__device__ float g_h1[ROWS * FFn];

__device__ __forceinline__ float warp_sum(float v) {
#pragma unroll
    for (int o = 16; o > 0; o >>= 1) v += __shfl_xor_sync(0xffffffffu, v, o);
    return v;
}

// ---------------- embedding + sinusoidal positions ----------------
__global__ void embed_kernel(const int* __restrict__ tok, const float* __restrict__ emb) {
    int idx = blockIdx.x * blockDim.x + threadIdx.x;   // over B*S*D
    int d  = idx & (Dm - 1);
    int bs = idx >> 7;
    int s  = bs & (Sn - 1);
    int v  = tok[bs];
    int i2 = d & ~1;  // 2*i for the pair (sin at 2i, cos at 2i+1)
    float div = expf(-(float)i2 * (logf(10000.0f) / (float)Dm));
    float arg = (float)s * div;
    float pe  = (d & 1) ? cosf(arg) : sinf(arg);
    g_x[idx] = emb[v * Dm + d] + pe;
}

// ---------------- tiled GEMM: C[M,N] = A[M,K] @ W[N,K]^T + bias (+epilogue) --------
// EPI: 0 = bias only, 1 = bias+relu, 2 = bias+residual
template <int EPI>
__global__ void __launch_bounds__(256) gemm64(
    const float* __restrict__ A, const float* __restrict__ W,
    const float* __restrict__ bias, const float* __restrict__ res,
    float* __restrict__ C, int N, int K)
{
    __shared__ float As[32][65];
    __shared__ float Bs[32][65];
    const int m0 = blockIdx.y * 64, n0 = blockIdx.x * 64;
    const int tid = threadIdx.x;
    const int tx = tid & 15, ty = tid >> 4;

    float acc[4][4];
#pragma unroll
    for (int i = 0; i < 4; i++)
#pragma unroll
        for (int j = 0; j < 4; j++) acc[i][j] = 0.f;

    for (int kc = 0; kc < K; kc += 32) {
#pragma unroll
        for (int i = 0; i < 8; i++) {
            int idx = i * 256 + tid;
            int r = idx >> 5, kk = idx & 31;
            As[kk][r] = A[(size_t)(m0 + r) * K + kc + kk];
            Bs[kk][r] = W[(size_t)(n0 + r) * K + kc + kk];
        }
        __syncthreads();
#pragma unroll
        for (int kk = 0; kk < 32; kk++) {
            float a[4], b[4];
#pragma unroll
            for (int i = 0; i < 4; i++) { a[i] = As[kk][ty * 4 + i]; b[i] = Bs[kk][tx * 4 + i]; }
#pragma unroll
            for (int i = 0; i < 4; i++)
#pragma unroll
                for (int j = 0; j < 4; j++) acc[i][j] = fmaf(a[i], b[j], acc[i][j]);
        }
        __syncthreads();
    }

#pragma unroll
    for (int i = 0; i < 4; i++) {
        int m = m0 + ty * 4 + i;
#pragma unroll
        for (int j = 0; j < 4; j++) {
            int n = n0 + tx * 4 + j;
            float v = acc[i][j] + bias[n];
            if (EPI == 1) v = fmaxf(v, 0.f);
            if (EPI == 2) v += res[(size_t)m * N + n];
            C[(size_t)m * N + n] = v;
        }
    }
}

// ---------------- local-window attention (online softmax, per-thread query) --------
// grid: (S/128, H, B), 128 threads. K/V window staged in SMEM (key-major rows of 64B).
__global__ void __launch_bounds__(128) attn_kernel() {
    __shared__ __align__(16) float Ks[384][16];
    __shared__ __align__(16) float Vs[384][16];
    const int q0 = blockIdx.x * 128;
    const int h = blockIdx.y, b = blockIdx.z;
    const int t = threadIdx.x;
    const int klo = max(0, q0 - LWn);
    const int khi = min(Sn - 1, q0 + 127 + LWn);
    const int nk  = khi - klo + 1;  // <= 384
    const float* base = g_qkv + (size_t)b * Sn * (3 * Dm);

    for (int i = t; i < nk; i += 128) {
        const float4* kp = (const float4*)(base + (size_t)(klo + i) * (3 * Dm) + Dm + h * HD);
        const float4* vp = (const float4*)(base + (size_t)(klo + i) * (3 * Dm) + 2 * Dm + h * HD);
        float4* kd = (float4*)Ks[i];
        float4* vd = (float4*)Vs[i];
#pragma unroll
        for (int j = 0; j < 4; j++) { kd[j] = kp[j]; vd[j] = vp[j]; }
    }

    const int q = q0 + t;
    float qr[16];
    {
        const float4* qp = (const float4*)(base + (size_t)q * (3 * Dm) + h * HD);
#pragma unroll
        for (int j = 0; j < 4; j++) {
            float4 f = qp[j];
            qr[j * 4 + 0] = f.x; qr[j * 4 + 1] = f.y; qr[j * 4 + 2] = f.z; qr[j * 4 + 3] = f.w;
        }
    }
    __syncthreads();

    const int jlo = max(0, q - LWn) - klo;
    const int jhi = min(Sn - 1, q + LWn) - klo;
    float m = -INFINITY, l = 0.f, acc[16];
#pragma unroll
    for (int d = 0; d < 16; d++) acc[d] = 0.f;

    for (int j = 0; j < nk; j++) {   // j uniform across the block -> SMEM broadcasts
        if (j < jlo || j > jhi) continue;
        float s = 0.f;
#pragma unroll
        for (int d = 0; d < 16; d++) s = fmaf(qr[d], Ks[j][d], s);
        s *= 0.25f;  // 1/sqrt(hd=16)
        float mnew = fmaxf(m, s);
        float p = __expf(s - mnew);
        if (mnew > m) {
            float c = __expf(m - mnew);
            l *= c;
#pragma unroll
            for (int d = 0; d < 16; d++) acc[d] *= c;
            m = mnew;
        }
        l += p;
#pragma unroll
        for (int d = 0; d < 16; d++) acc[d] = fmaf(p, Vs[j][d], acc[d]);
    }

    float inv = 1.f / l;
    float* cp = g_ctx + (size_t)(b * Sn + q) * Dm + h * HD;
#pragma unroll
    for (int d = 0; d < 16; d++) cp[d] = acc[d] * inv;
}

// ---------------- LayerNorm over D=128 (one block per row) ----------------
__global__ void __launch_bounds__(128) ln_kernel(
    const float* __restrict__ y, const float* __restrict__ g,
    const float* __restrict__ bb, float* __restrict__ xo)
{
    const int row = blockIdx.x, d = threadIdx.x;
    float v = y[(size_t)row * Dm + d];
    __shared__ float r1[4], r2[4];
    float s = warp_sum(v);
    if ((d & 31) == 0) r1[d >> 5] = s;
    __syncthreads();
    float mean = (r1[0] + r1[1] + r1[2] + r1[3]) * (1.f / Dm);
    float dv = v - mean;
    float s2 = warp_sum(dv * dv);
    if ((d & 31) == 0) r2[d >> 5] = s2;
    __syncthreads();
    float var = (r2[0] + r2[1] + r2[2] + r2[3]) * (1.f / Dm);
    xo[(size_t)row * Dm + d] = dv * rsqrtf(var + EPSf) * g[d] + bb[d];
}

// ---------------- final LN + linear head + softplus ----------------
__global__ void __launch_bounds__(128) final_kernel(
    const float* __restrict__ g, const float* __restrict__ bb,
    const float* __restrict__ Wout, const float* __restrict__ bout,
    float* __restrict__ out)
{
    const int row = blockIdx.x, d = threadIdx.x;
    float v = g_x[(size_t)row * Dm + d];
    __shared__ float r1[4], r2[4], r3[4];
    float s = warp_sum(v);
    if ((d & 31) == 0) r1[d >> 5] = s;
    __syncthreads();
    float mean = (r1[0] + r1[1] + r1[2] + r1[3]) * (1.f / Dm);
    float dv = v - mean;
    float s2 = warp_sum(dv * dv);
    if ((d & 31) == 0) r2[d >> 5] = s2;
    __syncthreads();
    float var = (r2[0] + r2[1] + r2[2] + r2[3]) * (1.f / Dm);
    float xn = dv * rsqrtf(var + EPSf) * g[d] + bb[d];
    float p = warp_sum(xn * Wout[d]);
    if ((d & 31) == 0) r3[d >> 5] = p;
    __syncthreads();
    if (d == 0) {
        float z = r3[0] + r3[1] + r3[2] + r3[3] + bout[0];
        out[row] = (z > 15.f) ? z : log1pf(expf(z));
    }
}

// ---------------- launch ----------------
extern "C" void kernel_launch(void* const* d_in, const int* in_sizes, int n_in,
                              void* d_out, int out_size)
{
    const int*   tok  = (const int*)d_in[0];
    const float* emb  = (const float*)d_in[1];
    const float* Wqkv = (const float*)d_in[2];
    const float* bqkv = (const float*)d_in[3];
    const float* Wo   = (const float*)d_in[4];
    const float* bo   = (const float*)d_in[5];
    const float* ln1g = (const float*)d_in[6];
    const float* ln1b = (const float*)d_in[7];
    const float* ln2g = (const float*)d_in[8];
    const float* ln2b = (const float*)d_in[9];
    const float* W1   = (const float*)d_in[10];
    const float* b1   = (const float*)d_in[11];
    const float* W2   = (const float*)d_in[12];
    const float* b2   = (const float*)d_in[13];
    const float* lnfg = (const float*)d_in[14];
    const float* lnfb = (const float*)d_in[15];
    const float* Wout = (const float*)d_in[16];
    const float* bout = (const float*)d_in[17];
    float* out = (float*)d_out;

    float *px, *py, *pqkv, *pctx, *ph1;
    cudaGetSymbolAddress((void**)&px,   g_x);
    cudaGetSymbolAddress((void**)&py,   g_y);
    cudaGetSymbolAddress((void**)&pqkv, g_qkv);
    cudaGetSymbolAddress((void**)&pctx, g_ctx);
    cudaGetSymbolAddress((void**)&ph1,  g_h1);

    embed_kernel<<<(ROWS * Dm) / 256, 256>>>(tok, emb);

    for (int l = 0; l < Lnum; l++) {
        const float* Wqkv_l = Wqkv + (size_t)l * 3 * Dm * Dm;
        const float* bqkv_l = bqkv + (size_t)l * 3 * Dm;
        const float* Wo_l   = Wo   + (size_t)l * Dm * Dm;
        const float* bo_l   = bo   + (size_t)l * Dm;
        const float* W1_l   = W1   + (size_t)l * FFn * Dm;
        const float* b1_l   = b1   + (size_t)l * FFn;
        const float* W2_l   = W2   + (size_t)l * Dm * FFn;
        const float* b2_l   = b2   + (size_t)l * Dm;

        // qkv = x @ Wqkv^T + bqkv
        gemm64<0><<<dim3(6, ROWS / 64), 256>>>(px, Wqkv_l, bqkv_l, nullptr, pqkv, 3 * Dm, Dm);
        // local attention
        attn_kernel<<<dim3(Sn / 128, Hn, Bn), 128>>>();
        // y = x + ctx @ Wo^T + bo ; x = LN1(y)
        gemm64<2><<<dim3(2, ROWS / 64), 256>>>(pctx, Wo_l, bo_l, px, py, Dm, Dm);
        ln_kernel<<<ROWS, 128>>>(py, ln1g + l * Dm, ln1b + l * Dm, px);
        // h1 = relu(x @ W1^T + b1)
        gemm64<1><<<dim3(4, ROWS / 64), 256>>>(px, W1_l, b1_l, nullptr, ph1, FFn, Dm);
        // y = x + h1 @ W2^T + b2 ; x = LN2(y)
        gemm64<2><<<dim3(2, ROWS / 64), 256>>>(ph1, W2_l, b2_l, px, py, Dm, FFn);
        ln_kernel<<<ROWS, 128>>>(py, ln2g + l * Dm, ln2b + l * Dm, px);
    }

    final_kernel<<<ROWS, 128>>>(lnfg, lnfb, Wout, bout, out);
}

// round 2
// speedup vs baseline: 1.1269x; 1.1269x over previous
#include <cuda_runtime.h>
#include <math.h>

#define Bn   8
#define Sn   1024
#define Dm   128
#define Hn   8
#define HD   16
#define FFn  256
#define Lnum 4
#define LWn  128
#define EPSf 1e-5f
#define ROWS (Bn * Sn)   // 8192

// ---------------- scratch (static device memory; no runtime allocs) ----------------
__device__ float g_x[ROWS * Dm];
__device__ float g_y[ROWS * Dm];
__device__ float g_qkv[ROWS * 3 * Dm];
__device__ float g_ctx[ROWS * Dm];
__device__ float g_h1[ROWS * FFn];

__device__ __forceinline__ float warp_sum(float v) {
#pragma unroll
    for (int o = 16; o > 0; o >>= 1) v += __shfl_xor_sync(0xffffffffu, v, o);
    return v;
}

// ---- packed f32x2 helpers (Blackwell dual-FP32) ----
__device__ __forceinline__ unsigned long long pk2(float x, float y) {
    unsigned long long r;
    asm("mov.b64 %0, {%1, %2};" : "=l"(r) : "f"(x), "f"(y));
    return r;
}
__device__ __forceinline__ void upk2(unsigned long long v, float& x, float& y) {
    asm("mov.b64 {%0, %1}, %2;" : "=f"(x), "=f"(y) : "l"(v));
}
__device__ __forceinline__ void fma2(unsigned long long& d, unsigned long long a, unsigned long long b) {
    asm("fma.rn.f32x2 %0, %1, %2, %0;" : "+l"(d) : "l"(a), "l"(b));
}

// ---------------- embedding + sinusoidal positions ----------------
__global__ void embed_kernel(const int* __restrict__ tok, const float* __restrict__ emb) {
    int idx = blockIdx.x * blockDim.x + threadIdx.x;   // over B*S*D
    int d  = idx & (Dm - 1);
    int bs = idx >> 7;
    int s  = bs & (Sn - 1);
    int v  = tok[bs];
    int i2 = d & ~1;  // 2*i for the pair (sin at 2i, cos at 2i+1)
    float div = expf(-(float)i2 * (logf(10000.0f) / (float)Dm));
    float arg = (float)s * div;
    float pe  = (d & 1) ? cosf(arg) : sinf(arg);
    g_x[idx] = emb[v * Dm + d] + pe;
}

// ---------------- tiled GEMM: C[M,N] = A[M,K] @ W[N,K]^T + bias (+epilogue) --------
// 128(M) x 64(N) block tile, 256 threads, 8x4 microtile via packed f32x2.
// EPI: 0 = bias only, 1 = bias+relu, 2 = bias+residual
template <int EPI>
__global__ void __launch_bounds__(256) gemm128x64(
    const float* __restrict__ A, const float* __restrict__ W,
    const float* __restrict__ bias, const float* __restrict__ res,
    float* __restrict__ C, int N, int K)
{
    // K-major staging, padded so store banks spread as (kk + r) mod 32.
    // As pad 130 (even) keeps 8B alignment for LDS.64 compute loads.
    __shared__ float As[32][130];
    __shared__ float Bs[32][65];

    const int m0 = blockIdx.y * 128, n0 = blockIdx.x * 64;
    const int tid = threadIdx.x;
    const int tx = tid & 15;        // n-group: cols n0 + tx + 16*j
    const int ty = tid >> 4;        // m-group: rows m0 + 8*ty + {0..7}

    unsigned long long acc2[4][4];  // [m-pair][j], each holds rows (8ty+2p, 8ty+2p+1)
#pragma unroll
    for (int p = 0; p < 4; p++)
#pragma unroll
        for (int j = 0; j < 4; j++) acc2[p][j] = 0ull;

    for (int kc = 0; kc < K; kc += 32) {
        // stage A tile: 128 rows x 32 kk (coalesced global, conflict-free STS)
#pragma unroll
        for (int i = 0; i < 16; i++) {
            int idx = i * 256 + tid;
            int r = idx >> 5, kk = idx & 31;
            As[kk][r] = A[(size_t)(m0 + r) * K + kc + kk];
        }
        // stage W tile: 64 rows x 32 kk
#pragma unroll
        for (int i = 0; i < 8; i++) {
            int idx = i * 256 + tid;
            int r = idx >> 5, kk = idx & 31;
            Bs[kk][r] = W[(size_t)(n0 + r) * K + kc + kk];
        }
        __syncthreads();

#pragma unroll
        for (int kk = 0; kk < 32; kk++) {
            unsigned long long a2[4];
#pragma unroll
            for (int p = 0; p < 4; p++)
                a2[p] = *reinterpret_cast<const unsigned long long*>(&As[kk][8 * ty + 2 * p]);
            unsigned long long bb[4];
#pragma unroll
            for (int j = 0; j < 4; j++) {
                float b = Bs[kk][tx + 16 * j];
                bb[j] = pk2(b, b);
            }
#pragma unroll
            for (int p = 0; p < 4; p++)
#pragma unroll
                for (int j = 0; j < 4; j++) fma2(acc2[p][j], a2[p], bb[j]);
        }
        __syncthreads();
    }

#pragma unroll
    for (int p = 0; p < 4; p++) {
#pragma unroll
        for (int j = 0; j < 4; j++) {
            int n = n0 + tx + 16 * j;
            float v0, v1;
            upk2(acc2[p][j], v0, v1);
            float bv = bias[n];
            int m = m0 + 8 * ty + 2 * p;
            float r0 = v0 + bv, r1 = v1 + bv;
            if (EPI == 1) { r0 = fmaxf(r0, 0.f); r1 = fmaxf(r1, 0.f); }
            if (EPI == 2) {
                r0 += res[(size_t)m * N + n];
                r1 += res[(size_t)(m + 1) * N + n];
            }
            C[(size_t)m * N + n] = r0;
            C[(size_t)(m + 1) * N + n] = r1;
        }
    }
}

// ---------------- local-window attention (online softmax, per-thread query) --------
// grid: (S/128, H, B), 128 threads. K/V window staged in SMEM (key-major rows of 64B).
__global__ void __launch_bounds__(128) attn_kernel() {
    __shared__ __align__(16) float Ks[384][16];
    __shared__ __align__(16) float Vs[384][16];
    const int q0 = blockIdx.x * 128;
    const int h = blockIdx.y, b = blockIdx.z;
    const int t = threadIdx.x;
    const int klo = max(0, q0 - LWn);
    const int khi = min(Sn - 1, q0 + 127 + LWn);
    const int nk  = khi - klo + 1;  // <= 384
    const float* base = g_qkv + (size_t)b * Sn * (3 * Dm);

    for (int i = t; i < nk; i += 128) {
        const float4* kp = (const float4*)(base + (size_t)(klo + i) * (3 * Dm) + Dm + h * HD);
        const float4* vp = (const float4*)(base + (size_t)(klo + i) * (3 * Dm) + 2 * Dm + h * HD);
        float4* kd = (float4*)Ks[i];
        float4* vd = (float4*)Vs[i];
#pragma unroll
        for (int j = 0; j < 4; j++) { kd[j] = kp[j]; vd[j] = vp[j]; }
    }

    const int q = q0 + t;
    float qr[16];
    {
        const float4* qp = (const float4*)(base + (size_t)q * (3 * Dm) + h * HD);
#pragma unroll
        for (int j = 0; j < 4; j++) {
            float4 f = qp[j];
            qr[j * 4 + 0] = f.x; qr[j * 4 + 1] = f.y; qr[j * 4 + 2] = f.z; qr[j * 4 + 3] = f.w;
        }
    }
    __syncthreads();

    const int jlo = max(0, q - LWn) - klo;
    const int jhi = min(Sn - 1, q + LWn) - klo;
    float m = -INFINITY, l = 0.f, acc[16];
#pragma unroll
    for (int d = 0; d < 16; d++) acc[d] = 0.f;

    for (int j = 0; j < nk; j++) {   // j uniform across the block -> SMEM broadcasts
        if (j < jlo || j > jhi) continue;
        float s = 0.f;
#pragma unroll
        for (int d = 0; d < 16; d++) s = fmaf(qr[d], Ks[j][d], s);
        s *= 0.25f;  // 1/sqrt(hd=16)
        float mnew = fmaxf(m, s);
        float p = __expf(s - mnew);
        if (mnew > m) {
            float c = __expf(m - mnew);
            l *= c;
#pragma unroll
            for (int d = 0; d < 16; d++) acc[d] *= c;
            m = mnew;
        }
        l += p;
#pragma unroll
        for (int d = 0; d < 16; d++) acc[d] = fmaf(p, Vs[j][d], acc[d]);
    }

    float inv = 1.f / l;
    float* cp = g_ctx + (size_t)(b * Sn + q) * Dm + h * HD;
#pragma unroll
    for (int d = 0; d < 16; d++) cp[d] = acc[d] * inv;
}

// ---------------- LayerNorm over D=128 (one block per row) ----------------
__global__ void __launch_bounds__(128) ln_kernel(
    const float* __restrict__ y, const float* __restrict__ g,
    const float* __restrict__ bb, float* __restrict__ xo)
{
    const int row = blockIdx.x, d = threadIdx.x;
    float v = y[(size_t)row * Dm + d];
    __shared__ float r1[4], r2[4];
    float s = warp_sum(v);
    if ((d & 31) == 0) r1[d >> 5] = s;
    __syncthreads();
    float mean = (r1[0] + r1[1] + r1[2] + r1[3]) * (1.f / Dm);
    float dv = v - mean;
    float s2 = warp_sum(dv * dv);
    if ((d & 31) == 0) r2[d >> 5] = s2;
    __syncthreads();
    float var = (r2[0] + r2[1] + r2[2] + r2[3]) * (1.f / Dm);
    xo[(size_t)row * Dm + d] = dv * rsqrtf(var + EPSf) * g[d] + bb[d];
}

// ---------------- final LN + linear head + softplus ----------------
__global__ void __launch_bounds__(128) final_kernel(
    const float* __restrict__ g, const float* __restrict__ bb,
    const float* __restrict__ Wout, const float* __restrict__ bout,
    float* __restrict__ out)
{
    const int row = blockIdx.x, d = threadIdx.x;
    float v = g_x[(size_t)row * Dm + d];
    __shared__ float r1[4], r2[4], r3[4];
    float s = warp_sum(v);
    if ((d & 31) == 0) r1[d >> 5] = s;
    __syncthreads();
    float mean = (r1[0] + r1[1] + r1[2] + r1[3]) * (1.f / Dm);
    float dv = v - mean;
    float s2 = warp_sum(dv * dv);
    if ((d & 31) == 0) r2[d >> 5] = s2;
    __syncthreads();
    float var = (r2[0] + r2[1] + r2[2] + r2[3]) * (1.f / Dm);
    float xn = dv * rsqrtf(var + EPSf) * g[d] + bb[d];
    float p = warp_sum(xn * Wout[d]);
    if ((d & 31) == 0) r3[d >> 5] = p;
    __syncthreads();
    if (d == 0) {
        float z = r3[0] + r3[1] + r3[2] + r3[3] + bout[0];
        out[row] = (z > 15.f) ? z : log1pf(expf(z));
    }
}

// ---------------- launch ----------------
extern "C" void kernel_launch(void* const* d_in, const int* in_sizes, int n_in,
                              void* d_out, int out_size)
{
    const int*   tok  = (const int*)d_in[0];
    const float* emb  = (const float*)d_in[1];
    const float* Wqkv = (const float*)d_in[2];
    const float* bqkv = (const float*)d_in[3];
    const float* Wo   = (const float*)d_in[4];
    const float* bo   = (const float*)d_in[5];
    const float* ln1g = (const float*)d_in[6];
    const float* ln1b = (const float*)d_in[7];
    const float* ln2g = (const float*)d_in[8];
    const float* ln2b = (const float*)d_in[9];
    const float* W1   = (const float*)d_in[10];
    const float* b1   = (const float*)d_in[11];
    const float* W2   = (const float*)d_in[12];
    const float* b2   = (const float*)d_in[13];
    const float* lnfg = (const float*)d_in[14];
    const float* lnfb = (const float*)d_in[15];
    const float* Wout = (const float*)d_in[16];
    const float* bout = (const float*)d_in[17];
    float* out = (float*)d_out;

    float *px, *py, *pqkv, *pctx, *ph1;
    cudaGetSymbolAddress((void**)&px,   g_x);
    cudaGetSymbolAddress((void**)&py,   g_y);
    cudaGetSymbolAddress((void**)&pqkv, g_qkv);
    cudaGetSymbolAddress((void**)&pctx, g_ctx);
    cudaGetSymbolAddress((void**)&ph1,  g_h1);

    embed_kernel<<<(ROWS * Dm) / 256, 256>>>(tok, emb);

    for (int l = 0; l < Lnum; l++) {
        const float* Wqkv_l = Wqkv + (size_t)l * 3 * Dm * Dm;
        const float* bqkv_l = bqkv + (size_t)l * 3 * Dm;
        const float* Wo_l   = Wo   + (size_t)l * Dm * Dm;
        const float* bo_l   = bo   + (size_t)l * Dm;
        const float* W1_l   = W1   + (size_t)l * FFn * Dm;
        const float* b1_l   = b1   + (size_t)l * FFn;
        const float* W2_l   = W2   + (size_t)l * Dm * FFn;
        const float* b2_l   = b2   + (size_t)l * Dm;

        // qkv = x @ Wqkv^T + bqkv
        gemm128x64<0><<<dim3(6, ROWS / 128), 256>>>(px, Wqkv_l, bqkv_l, nullptr, pqkv, 3 * Dm, Dm);
        // local attention
        attn_kernel<<<dim3(Sn / 128, Hn, Bn), 128>>>();
        // y = x + ctx @ Wo^T + bo ; x = LN1(y)
        gemm128x64<2><<<dim3(2, ROWS / 128), 256>>>(pctx, Wo_l, bo_l, px, py, Dm, Dm);
        ln_kernel<<<ROWS, 128>>>(py, ln1g + l * Dm, ln1b + l * Dm, px);
        // h1 = relu(x @ W1^T + b1)
        gemm128x64<1><<<dim3(4, ROWS / 128), 256>>>(px, W1_l, b1_l, nullptr, ph1, FFn, Dm);
        // y = x + h1 @ W2^T + b2 ; x = LN2(y)
        gemm128x64<2><<<dim3(2, ROWS / 128), 256>>>(ph1, W2_l, b2_l, px, py, Dm, FFn);
        ln_kernel<<<ROWS, 128>>>(py, ln2g + l * Dm, ln2b + l * Dm, px);
    }

    final_kernel<<<ROWS, 128>>>(lnfg, lnfb, Wout, bout, out);
}

// round 3
// speedup vs baseline: 1.1958x; 1.0611x over previous
#include <cuda_runtime.h>
#include <math.h>

#define Bn   8
#define Sn   1024
#define Dm   128
#define Hn   8
#define HD   16
#define FFn  256
#define Lnum 4
#define LWn  128
#define EPSf 1e-5f
#define ROWS (Bn * Sn)   // 8192

// ---------------- scratch (static device memory; no runtime allocs) ----------------
__device__ float g_x[ROWS * Dm];
__device__ float g_y[ROWS * Dm];
__device__ float g_qkv[ROWS * 3 * Dm];
__device__ float g_ctx[ROWS * Dm];
__device__ float g_h1[ROWS * FFn];

__device__ __forceinline__ float warp_sum(float v) {
#pragma unroll
    for (int o = 16; o > 0; o >>= 1) v += __shfl_xor_sync(0xffffffffu, v, o);
    return v;
}

// ---- packed f32x2 helpers (Blackwell dual-FP32) ----
__device__ __forceinline__ unsigned long long pk2(float x, float y) {
    unsigned long long r;
    asm("mov.b64 %0, {%1, %2};" : "=l"(r) : "f"(x), "f"(y));
    return r;
}
__device__ __forceinline__ void upk2(unsigned long long v, float& x, float& y) {
    asm("mov.b64 {%0, %1}, %2;" : "=f"(x), "=f"(y) : "l"(v));
}
__device__ __forceinline__ void fma2(unsigned long long& d, unsigned long long a, unsigned long long b) {
    asm("fma.rn.f32x2 %0, %1, %2, %0;" : "+l"(d) : "l"(a), "l"(b));
}

// ---------------- embedding + sinusoidal positions ----------------
__global__ void embed_kernel(const int* __restrict__ tok, const float* __restrict__ emb) {
    int idx = blockIdx.x * blockDim.x + threadIdx.x;   // over B*S*D
    int d  = idx & (Dm - 1);
    int bs = idx >> 7;
    int s  = bs & (Sn - 1);
    int v  = tok[bs];
    int i2 = d & ~1;  // 2*i for the pair (sin at 2i, cos at 2i+1)
    float div = expf(-(float)i2 * (logf(10000.0f) / (float)Dm));
    float arg = (float)s * div;
    float pe  = (d & 1) ? cosf(arg) : sinf(arg);
    g_x[idx] = emb[v * Dm + d] + pe;
}

// ---------------- tiled GEMM: C[M,N] = A[M,K] @ W[N,K]^T + bias (+epilogue) --------
// 64x64 block tile, 128 threads, 8x4 microtile via packed f32x2.
// Register-prefetch double-buffered staging (LDG of chunk i+1 overlaps compute of i).
// EPI: 0 = bias only, 1 = bias+relu, 2 = bias+residual
template <int EPI>
__global__ void __launch_bounds__(128) gemm64x64(
    const float* __restrict__ A, const float* __restrict__ W,
    const float* __restrict__ bias, const float* __restrict__ res,
    float* __restrict__ C, int N, int K)
{
    __shared__ float As[2][32][66];   // [buf][kk][m], pad 66 (even -> 8B-aligned pairs)
    __shared__ float Bs[2][32][66];   // [buf][kk][n]

    const int m0 = blockIdx.y * 64, n0 = blockIdx.x * 64;
    const int tid = threadIdx.x;
    const int tx = tid & 15;          // n-group: cols n0 + tx + 16*j
    const int ty = tid >> 4;          // m-group: rows m0 + 8*ty + {0..7}
    const int r8 = tid >> 3;          // staging row base (0..15)
    const int k4 = tid & 7;           // staging k-quad

    unsigned long long acc2[4][4];    // [m-pair p][j]: rows (8ty+2p, 8ty+2p+1)
#pragma unroll
    for (int p = 0; p < 4; p++)
#pragma unroll
        for (int j = 0; j < 4; j++) acc2[p][j] = 0ull;

    float4 apf[4], bpf[4];

    // prologue: prefetch chunk 0
#pragma unroll
    for (int i = 0; i < 4; i++) {
        int r = i * 16 + r8;
        apf[i] = *(const float4*)&A[(size_t)(m0 + r) * K + 4 * k4];
        bpf[i] = *(const float4*)&W[(size_t)(n0 + r) * K + 4 * k4];
    }

    int buf = 0;
    for (int kc = 0; kc < K; kc += 32, buf ^= 1) {
        // stage prefetched regs into smem (transpose to k-major), conflict-free banks
#pragma unroll
        for (int i = 0; i < 4; i++) {
            int r = i * 16 + r8;
#pragma unroll
            for (int c = 0; c < 4; c++) {
                As[buf][4 * k4 + c][r] = ((const float*)&apf[i])[c];
                Bs[buf][4 * k4 + c][r] = ((const float*)&bpf[i])[c];
            }
        }
        __syncthreads();

        // prefetch next chunk (overlaps compute below)
        if (kc + 32 < K) {
#pragma unroll
            for (int i = 0; i < 4; i++) {
                int r = i * 16 + r8;
                apf[i] = *(const float4*)&A[(size_t)(m0 + r) * K + kc + 32 + 4 * k4];
                bpf[i] = *(const float4*)&W[(size_t)(n0 + r) * K + kc + 32 + 4 * k4];
            }
        }

#pragma unroll
        for (int kk = 0; kk < 32; kk++) {
            unsigned long long a2[4];
#pragma unroll
            for (int p = 0; p < 4; p++)
                a2[p] = *reinterpret_cast<const unsigned long long*>(&As[buf][kk][8 * ty + 2 * p]);
            unsigned long long bb[4];
#pragma unroll
            for (int j = 0; j < 4; j++) {
                float b = Bs[buf][kk][tx + 16 * j];
                bb[j] = pk2(b, b);
            }
#pragma unroll
            for (int p = 0; p < 4; p++)
#pragma unroll
                for (int j = 0; j < 4; j++) fma2(acc2[p][j], a2[p], bb[j]);
        }
        // note: next iteration writes buf^1, and its __syncthreads guards reuse of buf
    }

#pragma unroll
    for (int p = 0; p < 4; p++) {
#pragma unroll
        for (int j = 0; j < 4; j++) {
            int n = n0 + tx + 16 * j;
            float v0, v1;
            upk2(acc2[p][j], v0, v1);
            float bv = bias[n];
            int m = m0 + 8 * ty + 2 * p;
            float r0 = v0 + bv, r1 = v1 + bv;
            if (EPI == 1) { r0 = fmaxf(r0, 0.f); r1 = fmaxf(r1, 0.f); }
            if (EPI == 2) {
                r0 += res[(size_t)m * N + n];
                r1 += res[(size_t)(m + 1) * N + n];
            }
            C[(size_t)m * N + n] = r0;
            C[(size_t)(m + 1) * N + n] = r1;
        }
    }
}

// ---------------- local-window attention (online softmax, per-thread query) --------
// grid: (S/128, H, B), 128 threads. K/V window staged in SMEM (key-major rows of 64B).
__global__ void __launch_bounds__(128) attn_kernel() {
    __shared__ __align__(16) float Ks[384][16];
    __shared__ __align__(16) float Vs[384][16];
    const int q0 = blockIdx.x * 128;
    const int h = blockIdx.y, b = blockIdx.z;
    const int t = threadIdx.x;
    const int klo = max(0, q0 - LWn);
    const int khi = min(Sn - 1, q0 + 127 + LWn);
    const int nk  = khi - klo + 1;  // <= 384
    const float* base = g_qkv + (size_t)b * Sn * (3 * Dm);

    for (int i = t; i < nk; i += 128) {
        const float4* kp = (const float4*)(base + (size_t)(klo + i) * (3 * Dm) + Dm + h * HD);
        const float4* vp = (const float4*)(base + (size_t)(klo + i) * (3 * Dm) + 2 * Dm + h * HD);
        float4* kd = (float4*)Ks[i];
        float4* vd = (float4*)Vs[i];
#pragma unroll
        for (int j = 0; j < 4; j++) { kd[j] = kp[j]; vd[j] = vp[j]; }
    }

    const int q = q0 + t;
    float qr[16];
    {
        const float4* qp = (const float4*)(base + (size_t)q * (3 * Dm) + h * HD);
#pragma unroll
        for (int j = 0; j < 4; j++) {
            float4 f = qp[j];
            qr[j * 4 + 0] = f.x; qr[j * 4 + 1] = f.y; qr[j * 4 + 2] = f.z; qr[j * 4 + 3] = f.w;
        }
    }
    __syncthreads();

    const int jlo = max(0, q - LWn) - klo;
    const int jhi = min(Sn - 1, q + LWn) - klo;
    float m = -INFINITY, l = 0.f, acc[16];
#pragma unroll
    for (int d = 0; d < 16; d++) acc[d] = 0.f;

    for (int j = 0; j < nk; j++) {   // j uniform across the block -> SMEM broadcasts
        if (j < jlo || j > jhi) continue;
        float s = 0.f;
#pragma unroll
        for (int d = 0; d < 16; d++) s = fmaf(qr[d], Ks[j][d], s);
        s *= 0.25f;  // 1/sqrt(hd=16)
        float mnew = fmaxf(m, s);
        float p = __expf(s - mnew);
        if (mnew > m) {
            float c = __expf(m - mnew);
            l *= c;
#pragma unroll
            for (int d = 0; d < 16; d++) acc[d] *= c;
            m = mnew;
        }
        l += p;
#pragma unroll
        for (int d = 0; d < 16; d++) acc[d] = fmaf(p, Vs[j][d], acc[d]);
    }

    float inv = 1.f / l;
    float* cp = g_ctx + (size_t)(b * Sn + q) * Dm + h * HD;
#pragma unroll
    for (int d = 0; d < 16; d++) cp[d] = acc[d] * inv;
}

// ---------------- LayerNorm over D=128 (one block per row) ----------------
__global__ void __launch_bounds__(128) ln_kernel(
    const float* __restrict__ y, const float* __restrict__ g,
    const float* __restrict__ bb, float* __restrict__ xo)
{
    const int row = blockIdx.x, d = threadIdx.x;
    float v = y[(size_t)row * Dm + d];
    __shared__ float r1[4], r2[4];
    float s = warp_sum(v);
    if ((d & 31) == 0) r1[d >> 5] = s;
    __syncthreads();
    float mean = (r1[0] + r1[1] + r1[2] + r1[3]) * (1.f / Dm);
    float dv = v - mean;
    float s2 = warp_sum(dv * dv);
    if ((d & 31) == 0) r2[d >> 5] = s2;
    __syncthreads();
    float var = (r2[0] + r2[1] + r2[2] + r2[3]) * (1.f / Dm);
    xo[(size_t)row * Dm + d] = dv * rsqrtf(var + EPSf) * g[d] + bb[d];
}

// ---------------- final LN + linear head + softplus ----------------
__global__ void __launch_bounds__(128) final_kernel(
    const float* __restrict__ g, const float* __restrict__ bb,
    const float* __restrict__ Wout, const float* __restrict__ bout,
    float* __restrict__ out)
{
    const int row = blockIdx.x, d = threadIdx.x;
    float v = g_x[(size_t)row * Dm + d];
    __shared__ float r1[4], r2[4], r3[4];
    float s = warp_sum(v);
    if ((d & 31) == 0) r1[d >> 5] = s;
    __syncthreads();
    float mean = (r1[0] + r1[1] + r1[2] + r1[3]) * (1.f / Dm);
    float dv = v - mean;
    float s2 = warp_sum(dv * dv);
    if ((d & 31) == 0) r2[d >> 5] = s2;
    __syncthreads();
    float var = (r2[0] + r2[1] + r2[2] + r2[3]) * (1.f / Dm);
    float xn = dv * rsqrtf(var + EPSf) * g[d] + bb[d];
    float p = warp_sum(xn * Wout[d]);
    if ((d & 31) == 0) r3[d >> 5] = p;
    __syncthreads();
    if (d == 0) {
        float z = r3[0] + r3[1] + r3[2] + r3[3] + bout[0];
        out[row] = (z > 15.f) ? z : log1pf(expf(z));
    }
}

// ---------------- launch ----------------
extern "C" void kernel_launch(void* const* d_in, const int* in_sizes, int n_in,
                              void* d_out, int out_size)
{
    const int*   tok  = (const int*)d_in[0];
    const float* emb  = (const float*)d_in[1];
    const float* Wqkv = (const float*)d_in[2];
    const float* bqkv = (const float*)d_in[3];
    const float* Wo   = (const float*)d_in[4];
    const float* bo   = (const float*)d_in[5];
    const float* ln1g = (const float*)d_in[6];
    const float* ln1b = (const float*)d_in[7];
    const float* ln2g = (const float*)d_in[8];
    const float* ln2b = (const float*)d_in[9];
    const float* W1   = (const float*)d_in[10];
    const float* b1   = (const float*)d_in[11];
    const float* W2   = (const float*)d_in[12];
    const float* b2   = (const float*)d_in[13];
    const float* lnfg = (const float*)d_in[14];
    const float* lnfb = (const float*)d_in[15];
    const float* Wout = (const float*)d_in[16];
    const float* bout = (const float*)d_in[17];
    float* out = (float*)d_out;

    float *px, *py, *pqkv, *pctx, *ph1;
    cudaGetSymbolAddress((void**)&px,   g_x);
    cudaGetSymbolAddress((void**)&py,   g_y);
    cudaGetSymbolAddress((void**)&pqkv, g_qkv);
    cudaGetSymbolAddress((void**)&pctx, g_ctx);
    cudaGetSymbolAddress((void**)&ph1,  g_h1);

    embed_kernel<<<(ROWS * Dm) / 256, 256>>>(tok, emb);

    for (int l = 0; l < Lnum; l++) {
        const float* Wqkv_l = Wqkv + (size_t)l * 3 * Dm * Dm;
        const float* bqkv_l = bqkv + (size_t)l * 3 * Dm;
        const float* Wo_l   = Wo   + (size_t)l * Dm * Dm;
        const float* bo_l   = bo   + (size_t)l * Dm;
        const float* W1_l   = W1   + (size_t)l * FFn * Dm;
        const float* b1_l   = b1   + (size_t)l * FFn;
        const float* W2_l   = W2   + (size_t)l * Dm * FFn;
        const float* b2_l   = b2   + (size_t)l * Dm;

        // qkv = x @ Wqkv^T + bqkv
        gemm64x64<0><<<dim3(6, ROWS / 64), 128>>>(px, Wqkv_l, bqkv_l, nullptr, pqkv, 3 * Dm, Dm);
        // local attention
        attn_kernel<<<dim3(Sn / 128, Hn, Bn), 128>>>();
        // y = x + ctx @ Wo^T + bo ; x = LN1(y)
        gemm64x64<2><<<dim3(2, ROWS / 64), 128>>>(pctx, Wo_l, bo_l, px, py, Dm, Dm);
        ln_kernel<<<ROWS, 128>>>(py, ln1g + l * Dm, ln1b + l * Dm, px);
        // h1 = relu(x @ W1^T + b1)
        gemm64x64<1><<<dim3(4, ROWS / 64), 128>>>(px, W1_l, b1_l, nullptr, ph1, FFn, Dm);
        // y = x + h1 @ W2^T + b2 ; x = LN2(y)
        gemm64x64<2><<<dim3(2, ROWS / 64), 128>>>(ph1, W2_l, b2_l, px, py, Dm, FFn);
        ln_kernel<<<ROWS, 128>>>(py, ln2g + l * Dm, ln2b + l * Dm, px);
    }

    final_kernel<<<ROWS, 128>>>(lnfg, lnfb, Wout, bout, out);
}

// round 4
// speedup vs baseline: 1.3707x; 1.1463x over previous
#include <cuda_runtime.h>
#include <math.h>

#define Bn   8
#define Sn   1024
#define Dm   128
#define Hn   8
#define HD   16
#define FFn  256
#define Lnum 4
#define LWn  128
#define EPSf 1e-5f
#define ROWS (Bn * Sn)   // 8192

typedef unsigned long long u64;

// ---------------- scratch (static device memory; no runtime allocs) ----------------
__device__ float g_x[ROWS * Dm];
__device__ float g_qkv[ROWS * 3 * Dm];
__device__ float g_ctx[ROWS * Dm];
__device__ float g_h1[ROWS * FFn];

__device__ __forceinline__ float warp_sum(float v) {
#pragma unroll
    for (int o = 16; o > 0; o >>= 1) v += __shfl_xor_sync(0xffffffffu, v, o);
    return v;
}

// ---- packed f32x2 helpers (Blackwell dual-FP32) ----
__device__ __forceinline__ u64 pk2(float x, float y) {
    u64 r;
    asm("mov.b64 %0, {%1, %2};" : "=l"(r) : "f"(x), "f"(y));
    return r;
}
__device__ __forceinline__ void upk2(u64 v, float& x, float& y) {
    asm("mov.b64 {%0, %1}, %2;" : "=f"(x), "=f"(y) : "l"(v));
}
__device__ __forceinline__ void fma2(u64& d, u64 a, u64 b) {
    asm("fma.rn.f32x2 %0, %1, %2, %0;" : "+l"(d) : "l"(a), "l"(b));
}

// ---------------- embedding + sinusoidal positions ----------------
__global__ void embed_kernel(const int* __restrict__ tok, const float* __restrict__ emb) {
    int idx = blockIdx.x * blockDim.x + threadIdx.x;   // over B*S*D
    int d  = idx & (Dm - 1);
    int bs = idx >> 7;
    int s  = bs & (Sn - 1);
    int v  = tok[bs];
    int i2 = d & ~1;
    float div = expf(-(float)i2 * (logf(10000.0f) / (float)Dm));
    float arg = (float)s * div;
    float pe  = (d & 1) ? cosf(arg) : sinf(arg);
    g_x[idx] = emb[v * Dm + d] + pe;
}

// ---------------- GEMM 64x64: C = A @ W^T + bias (+relu) ----------------
// 128 threads, 8x4 f32x2 microtile, double-buffered smem + register kk-pipeline.
// EPI: 0 = bias, 1 = bias+relu
template <int EPI>
__global__ void __launch_bounds__(128) gemm64x64(
    const float* __restrict__ A, const float* __restrict__ W,
    const float* __restrict__ bias, float* __restrict__ C, int N, int K)
{
    __shared__ float As[2][32][66];
    __shared__ float Bs[2][32][66];

    const int m0 = blockIdx.y * 64, n0 = blockIdx.x * 64;
    const int tid = threadIdx.x;
    const int tx = tid & 15;
    const int ty = tid >> 4;
    const int r8 = tid >> 3;
    const int k4 = tid & 7;

    u64 acc2[4][4];
#pragma unroll
    for (int p = 0; p < 4; p++)
#pragma unroll
        for (int j = 0; j < 4; j++) acc2[p][j] = 0ull;

    float4 apf[4], bpf[4];
#pragma unroll
    for (int i = 0; i < 4; i++) {
        int r = i * 16 + r8;
        apf[i] = *(const float4*)&A[(size_t)(m0 + r) * K + 4 * k4];
        bpf[i] = *(const float4*)&W[(size_t)(n0 + r) * K + 4 * k4];
    }

    int buf = 0;
    for (int kc = 0; kc < K; kc += 32, buf ^= 1) {
#pragma unroll
        for (int i = 0; i < 4; i++) {
            int r = i * 16 + r8;
#pragma unroll
            for (int c = 0; c < 4; c++) {
                As[buf][4 * k4 + c][r] = ((const float*)&apf[i])[c];
                Bs[buf][4 * k4 + c][r] = ((const float*)&bpf[i])[c];
            }
        }
        __syncthreads();

        if (kc + 32 < K) {
#pragma unroll
            for (int i = 0; i < 4; i++) {
                int r = i * 16 + r8;
                apf[i] = *(const float4*)&A[(size_t)(m0 + r) * K + kc + 32 + 4 * k4];
                bpf[i] = *(const float4*)&W[(size_t)(n0 + r) * K + kc + 32 + 4 * k4];
            }
        }

        u64 a2c[4], bbc[4];
#pragma unroll
        for (int p = 0; p < 4; p++) a2c[p] = *(const u64*)&As[buf][0][8 * ty + 2 * p];
#pragma unroll
        for (int j = 0; j < 4; j++) { float b = Bs[buf][0][tx + 16 * j]; bbc[j] = pk2(b, b); }

#pragma unroll
        for (int kk = 0; kk < 32; kk++) {
            u64 a2n[4], bbn[4];
            int kn = (kk + 1) & 31;
#pragma unroll
            for (int p = 0; p < 4; p++) a2n[p] = *(const u64*)&As[buf][kn][8 * ty + 2 * p];
#pragma unroll
            for (int j = 0; j < 4; j++) { float b = Bs[buf][kn][tx + 16 * j]; bbn[j] = pk2(b, b); }
#pragma unroll
            for (int p = 0; p < 4; p++)
#pragma unroll
                for (int j = 0; j < 4; j++) fma2(acc2[p][j], a2c[p], bbc[j]);
#pragma unroll
            for (int p = 0; p < 4; p++) a2c[p] = a2n[p];
#pragma unroll
            for (int j = 0; j < 4; j++) bbc[j] = bbn[j];
        }
        __syncthreads();
    }

#pragma unroll
    for (int p = 0; p < 4; p++) {
#pragma unroll
        for (int j = 0; j < 4; j++) {
            int n = n0 + tx + 16 * j;
            float v0, v1;
            upk2(acc2[p][j], v0, v1);
            float bv = bias[n];
            int m = m0 + 8 * ty + 2 * p;
            float r0 = v0 + bv, r1 = v1 + bv;
            if (EPI == 1) { r0 = fmaxf(r0, 0.f); r1 = fmaxf(r1, 0.f); }
            C[(size_t)m * N + n] = r0;
            C[(size_t)(m + 1) * N + n] = r1;
        }
    }
}

// ---------------- GEMM 64x128 + bias + residual + LayerNorm fused -------------------
// N must be 128 (= Dm). 256 threads; warp w owns rows 8w..8w+7 fully -> LN via shuffles.
__global__ void __launch_bounds__(256) gemm_ln(
    const float* __restrict__ A, const float* __restrict__ W,
    const float* __restrict__ bias, const float* __restrict__ res,
    const float* __restrict__ lng, const float* __restrict__ lnb,
    float* __restrict__ C, int K)
{
    __shared__ float As[2][32][66];
    __shared__ float Bs[2][32][130];

    const int m0 = blockIdx.x * 64;
    const int tid = threadIdx.x;
    const int tx = tid & 31;
    const int ty = tid >> 5;
    const int r8 = tid >> 3;   // 0..31
    const int k4 = tid & 7;

    u64 acc2[4][4];   // [p][j]: rows (8ty+2p, +1), col tx+32j
#pragma unroll
    for (int p = 0; p < 4; p++)
#pragma unroll
        for (int j = 0; j < 4; j++) acc2[p][j] = 0ull;

    float4 apf[2], bpf[4];
#pragma unroll
    for (int i = 0; i < 2; i++) {
        int idx = i * 256 + tid;
        apf[i] = *(const float4*)&A[(size_t)(m0 + (idx >> 3)) * K + 4 * (idx & 7)];
    }
#pragma unroll
    for (int i = 0; i < 4; i++) {
        int idx = i * 256 + tid;
        bpf[i] = *(const float4*)&W[(size_t)(idx >> 3) * K + 4 * (idx & 7)];
    }

    int buf = 0;
    for (int kc = 0; kc < K; kc += 32, buf ^= 1) {
#pragma unroll
        for (int i = 0; i < 2; i++) {
            int idx = i * 256 + tid;
            int r = idx >> 3, kq = idx & 7;
#pragma unroll
            for (int c = 0; c < 4; c++) As[buf][4 * kq + c][r] = ((const float*)&apf[i])[c];
        }
#pragma unroll
        for (int i = 0; i < 4; i++) {
            int idx = i * 256 + tid;
            int r = idx >> 3, kq = idx & 7;
#pragma unroll
            for (int c = 0; c < 4; c++) Bs[buf][4 * kq + c][r] = ((const float*)&bpf[i])[c];
        }
        __syncthreads();

        if (kc + 32 < K) {
#pragma unroll
            for (int i = 0; i < 2; i++) {
                int idx = i * 256 + tid;
                apf[i] = *(const float4*)&A[(size_t)(m0 + (idx >> 3)) * K + kc + 32 + 4 * (idx & 7)];
            }
#pragma unroll
            for (int i = 0; i < 4; i++) {
                int idx = i * 256 + tid;
                bpf[i] = *(const float4*)&W[(size_t)(idx >> 3) * K + kc + 32 + 4 * (idx & 7)];
            }
        }

        u64 a2c[4], bbc[4];
#pragma unroll
        for (int p = 0; p < 4; p++) a2c[p] = *(const u64*)&As[buf][0][8 * ty + 2 * p];
#pragma unroll
        for (int j = 0; j < 4; j++) { float b = Bs[buf][0][tx + 32 * j]; bbc[j] = pk2(b, b); }

#pragma unroll
        for (int kk = 0; kk < 32; kk++) {
            u64 a2n[4], bbn[4];
            int kn = (kk + 1) & 31;
#pragma unroll
            for (int p = 0; p < 4; p++) a2n[p] = *(const u64*)&As[buf][kn][8 * ty + 2 * p];
#pragma unroll
            for (int j = 0; j < 4; j++) { float b = Bs[buf][kn][tx + 32 * j]; bbn[j] = pk2(b, b); }
#pragma unroll
            for (int p = 0; p < 4; p++)
#pragma unroll
                for (int j = 0; j < 4; j++) fma2(acc2[p][j], a2c[p], bbc[j]);
#pragma unroll
            for (int p = 0; p < 4; p++) a2c[p] = a2n[p];
#pragma unroll
            for (int j = 0; j < 4; j++) bbc[j] = bbn[j];
        }
        __syncthreads();
    }

    // epilogue: y = acc + bias + res ; out = LN(y) * g + b, all within one warp per row
    float bv[4], gv[4], lb[4];
#pragma unroll
    for (int j = 0; j < 4; j++) {
        int n = tx + 32 * j;
        bv[j] = bias[n]; gv[j] = lng[n]; lb[j] = lnb[n];
    }
#pragma unroll
    for (int p = 0; p < 4; p++) {
        int m = m0 + 8 * ty + 2 * p;
        float v0[4], v1[4];
        float s0 = 0.f, s1 = 0.f, q0 = 0.f, q1 = 0.f;
#pragma unroll
        for (int j = 0; j < 4; j++) {
            int n = tx + 32 * j;
            float x0, x1;
            upk2(acc2[p][j], x0, x1);
            v0[j] = x0 + bv[j] + res[(size_t)m * Dm + n];
            v1[j] = x1 + bv[j] + res[(size_t)(m + 1) * Dm + n];
            s0 += v0[j]; s1 += v1[j];
            q0 = fmaf(v0[j], v0[j], q0); q1 = fmaf(v1[j], v1[j], q1);
        }
        s0 = warp_sum(s0); s1 = warp_sum(s1);
        q0 = warp_sum(q0); q1 = warp_sum(q1);
        float mu0 = s0 * (1.f / Dm), mu1 = s1 * (1.f / Dm);
        float var0 = fmaf(-mu0, mu0, q0 * (1.f / Dm));
        float var1 = fmaf(-mu1, mu1, q1 * (1.f / Dm));
        float rs0 = rsqrtf(var0 + EPSf), rs1 = rsqrtf(var1 + EPSf);
#pragma unroll
        for (int j = 0; j < 4; j++) {
            int n = tx + 32 * j;
            C[(size_t)m * Dm + n]       = (v0[j] - mu0) * rs0 * gv[j] + lb[j];
            C[(size_t)(m + 1) * Dm + n] = (v1[j] - mu1) * rs1 * gv[j] + lb[j];
        }
    }
}

// ---------------- local-window attention (f32x2, unnormalized-exp softmax) ----------
__global__ void __launch_bounds__(128) attn_kernel() {
    __shared__ __align__(16) float Ks[384][16];
    __shared__ __align__(16) float Vs[384][16];
    const int q0 = blockIdx.x * 128;
    const int h = blockIdx.y, b = blockIdx.z;
    const int t = threadIdx.x;
    const int klo = max(0, q0 - LWn);
    const int khi = min(Sn - 1, q0 + 127 + LWn);
    const int nk  = khi - klo + 1;  // <= 384
    const float* base = g_qkv + (size_t)b * Sn * (3 * Dm);

    for (int i = t; i < nk; i += 128) {
        const float4* kp = (const float4*)(base + (size_t)(klo + i) * (3 * Dm) + Dm + h * HD);
        const float4* vp = (const float4*)(base + (size_t)(klo + i) * (3 * Dm) + 2 * Dm + h * HD);
        float4* kd = (float4*)Ks[i];
        float4* vd = (float4*)Vs[i];
#pragma unroll
        for (int j = 0; j < 4; j++) { kd[j] = kp[j]; vd[j] = vp[j]; }
    }

    const int q = q0 + t;
    u64 q2[8];
    {
        const float4* qp = (const float4*)(base + (size_t)q * (3 * Dm) + h * HD);
#pragma unroll
        for (int j = 0; j < 4; j++) {
            float4 f = qp[j];
            q2[2 * j]     = pk2(0.25f * f.x, 0.25f * f.y);   // fold 1/sqrt(16)
            q2[2 * j + 1] = pk2(0.25f * f.z, 0.25f * f.w);
        }
    }
    __syncthreads();

    const int jlo = max(0, q - LWn) - klo;
    const int jhi = min(Sn - 1, q + LWn) - klo;
    float l = 0.f;
    u64 acc2[8];
#pragma unroll
    for (int d = 0; d < 8; d++) acc2[d] = 0ull;

    for (int j = 0; j < nk; j++) {   // j uniform -> all SMEM reads are broadcasts
        const u64* kr = (const u64*)Ks[j];
        u64 dp0 = 0ull, dp1 = 0ull;
#pragma unroll
        for (int d = 0; d < 8; d += 2) { fma2(dp0, q2[d], kr[d]); fma2(dp1, q2[d + 1], kr[d + 1]); }
        float ax, ay, bx, by;
        upk2(dp0, ax, ay); upk2(dp1, bx, by);
        float s = (ax + ay) + (bx + by);
        float w = (j >= jlo && j <= jhi) ? 1.f : 0.f;
        float p = __expf(s) * w;
        l += p;
        u64 pp = pk2(p, p);
        const u64* vr = (const u64*)Vs[j];
#pragma unroll
        for (int d = 0; d < 8; d++) fma2(acc2[d], pp, vr[d]);
    }

    float inv = 1.f / l;
    float* cp = g_ctx + (size_t)(b * Sn + q) * Dm + h * HD;
#pragma unroll
    for (int d = 0; d < 8; d++) {
        float x, y;
        upk2(acc2[d], x, y);
        cp[2 * d] = x * inv; cp[2 * d + 1] = y * inv;
    }
}

// ---------------- final LN + linear head + softplus ----------------
__global__ void __launch_bounds__(128) final_kernel(
    const float* __restrict__ g, const float* __restrict__ bb,
    const float* __restrict__ Wout, const float* __restrict__ bout,
    float* __restrict__ out)
{
    const int row = blockIdx.x, d = threadIdx.x;
    float v = g_x[(size_t)row * Dm + d];
    __shared__ float r1[4], r2[4], r3[4];
    float s = warp_sum(v);
    if ((d & 31) == 0) r1[d >> 5] = s;
    __syncthreads();
    float mean = (r1[0] + r1[1] + r1[2] + r1[3]) * (1.f / Dm);
    float dv = v - mean;
    float s2 = warp_sum(dv * dv);
    if ((d & 31) == 0) r2[d >> 5] = s2;
    __syncthreads();
    float var = (r2[0] + r2[1] + r2[2] + r2[3]) * (1.f / Dm);
    float xn = dv * rsqrtf(var + EPSf) * g[d] + bb[d];
    float p = warp_sum(xn * Wout[d]);
    if ((d & 31) == 0) r3[d >> 5] = p;
    __syncthreads();
    if (d == 0) {
        float z = r3[0] + r3[1] + r3[2] + r3[3] + bout[0];
        out[row] = (z > 15.f) ? z : log1pf(expf(z));
    }
}

// ---------------- launch ----------------
extern "C" void kernel_launch(void* const* d_in, const int* in_sizes, int n_in,
                              void* d_out, int out_size)
{
    const int*   tok  = (const int*)d_in[0];
    const float* emb  = (const float*)d_in[1];
    const float* Wqkv = (const float*)d_in[2];
    const float* bqkv = (const float*)d_in[3];
    const float* Wo   = (const float*)d_in[4];
    const float* bo   = (const float*)d_in[5];
    const float* ln1g = (const float*)d_in[6];
    const float* ln1b = (const float*)d_in[7];
    const float* ln2g = (const float*)d_in[8];
    const float* ln2b = (const float*)d_in[9];
    const float* W1   = (const float*)d_in[10];
    const float* b1   = (const float*)d_in[11];
    const float* W2   = (const float*)d_in[12];
    const float* b2   = (const float*)d_in[13];
    const float* lnfg = (const float*)d_in[14];
    const float* lnfb = (const float*)d_in[15];
    const float* Wout = (const float*)d_in[16];
    const float* bout = (const float*)d_in[17];
    float* out = (float*)d_out;

    float *px, *pqkv, *pctx, *ph1;
    cudaGetSymbolAddress((void**)&px,   g_x);
    cudaGetSymbolAddress((void**)&pqkv, g_qkv);
    cudaGetSymbolAddress((void**)&pctx, g_ctx);
    cudaGetSymbolAddress((void**)&ph1,  g_h1);

    embed_kernel<<<(ROWS * Dm) / 256, 256>>>(tok, emb);

    for (int l = 0; l < Lnum; l++) {
        const float* Wqkv_l = Wqkv + (size_t)l * 3 * Dm * Dm;
        const float* bqkv_l = bqkv + (size_t)l * 3 * Dm;
        const float* Wo_l   = Wo   + (size_t)l * Dm * Dm;
        const float* bo_l   = bo   + (size_t)l * Dm;
        const float* W1_l   = W1   + (size_t)l * FFn * Dm;
        const float* b1_l   = b1   + (size_t)l * FFn;
        const float* W2_l   = W2   + (size_t)l * Dm * FFn;
        const float* b2_l   = b2   + (size_t)l * Dm;

        // qkv = x @ Wqkv^T + bqkv
        gemm64x64<0><<<dim3(6, ROWS / 64), 128>>>(px, Wqkv_l, bqkv_l, pqkv, 3 * Dm, Dm);
        // local attention
        attn_kernel<<<dim3(Sn / 128, Hn, Bn), 128>>>();
        // x = LN1(x + ctx @ Wo^T + bo)   [fused]
        gemm_ln<<<ROWS / 64, 256>>>(pctx, Wo_l, bo_l, px, ln1g + l * Dm, ln1b + l * Dm, px, Dm);
        // h1 = relu(x @ W1^T + b1)
        gemm64x64<1><<<dim3(4, ROWS / 64), 128>>>(px, W1_l, b1_l, ph1, FFn, Dm);
        // x = LN2(x + h1 @ W2^T + b2)    [fused]
        gemm_ln<<<ROWS / 64, 256>>>(ph1, W2_l, b2_l, px, ln2g + l * Dm, ln2b + l * Dm, px, FFn);
    }

    final_kernel<<<ROWS, 128>>>(lnfg, lnfb, Wout, bout, out);
}